// round 15
// baseline (speedup 1.0000x reference)
#include <cuda_runtime.h>
#include <cuda_bf16.h>
#include <cuda_fp16.h>

// ---------------------------------------------------------------------------
// SelfAttention_50500225466674
// out = -(1/beta) * sum_{h,q} logsumexp_k( beta * (x Wq^T)[q,h,:] . (x Wk^T)[k,h,:] )
// N=2048, D=128, H=32, Z=64, beta = 1/sqrt(128)
// Stage 0: fp32 -> fp16 conversion of x, Wq, Wk (+ reset done-counter)
// Stage 1: fp16 HMMA projection Q and K (f32 acc), sqrt(beta*log2e) in both
// Stage 2: fused score GEMM (f16 acc, zero-init MMA) + online base-2 lse.
//          Q fragments streamed per k-chunk. __launch_bounds__(256,4):
//          4 CTAs/SM -> 592 slots >= 512 CTAs -> SINGLE WAVE (kills the
//          2x wave quantization measured in R12/R13).
//          Last-done CTA performs the final deterministic reduction.
// ---------------------------------------------------------------------------

#define NTOK 2048
#define DIM  128
#define NH   32
#define ZD   64

static __device__ __half g_x16[(size_t)NTOK * DIM];            // 0.5 MB
static __device__ __half g_W16[(size_t)2 * NH * ZD * DIM];     // 1 MB (Wq|Wk)
static __device__ __half g_Q[(size_t)NH * NTOK * ZD];          // 8 MB
static __device__ __half g_K[(size_t)NH * NTOK * ZD];          // 8 MB
static __device__ float g_partial[16 * NH];                    // 512 partials
static __device__ unsigned g_done;                             // CTA counter

// sqrt(log2(e)/sqrt(128)) : folded into both Q and K
#define QK_SCALE 0.3570959f

// ---------------- PTX helpers ----------------
__device__ __forceinline__ void ldsm4(unsigned addr, unsigned &r0, unsigned &r1,
                                      unsigned &r2, unsigned &r3) {
    asm volatile("ldmatrix.sync.aligned.m8n8.x4.shared.b16 {%0,%1,%2,%3}, [%4];"
                 : "=r"(r0), "=r"(r1), "=r"(r2), "=r"(r3)
                 : "r"(addr));
}

// f16 inputs, f32 accumulators (projection)
__device__ __forceinline__ void mma_f16_f32(float *c, unsigned a0, unsigned a1,
                                            unsigned a2, unsigned a3,
                                            unsigned b0, unsigned b1) {
    asm volatile(
        "mma.sync.aligned.m16n8k16.row.col.f32.f16.f16.f32 "
        "{%0,%1,%2,%3}, {%4,%5,%6,%7}, {%8,%9}, {%0,%1,%2,%3};"
        : "+f"(c[0]), "+f"(c[1]), "+f"(c[2]), "+f"(c[3])
        : "r"(a0), "r"(a1), "r"(a2), "r"(a3), "r"(b0), "r"(b1));
}

// f16 inputs, f16 accumulators, accumulate into C=D
__device__ __forceinline__ void mma_f16_f16(unsigned &c0, unsigned &c1,
                                            unsigned a0, unsigned a1,
                                            unsigned a2, unsigned a3,
                                            unsigned b0, unsigned b1) {
    asm volatile(
        "mma.sync.aligned.m16n8k16.row.col.f16.f16.f16.f16 "
        "{%0,%1}, {%2,%3,%4,%5}, {%6,%7}, {%0,%1};"
        : "+r"(c0), "+r"(c1)
        : "r"(a0), "r"(a1), "r"(a2), "r"(a3), "r"(b0), "r"(b1));
}

// f16 inputs, f16 accumulators, C = 0 (fresh init, no bank zeroing)
__device__ __forceinline__ void mma_f16_f16_z(unsigned &c0, unsigned &c1,
                                              unsigned a0, unsigned a1,
                                              unsigned a2, unsigned a3,
                                              unsigned b0, unsigned b1) {
    asm volatile(
        "mma.sync.aligned.m16n8k16.row.col.f16.f16.f16.f16 "
        "{%0,%1}, {%2,%3,%4,%5}, {%6,%7}, {%8,%9};"
        : "=r"(c0), "=r"(c1)
        : "r"(a0), "r"(a1), "r"(a2), "r"(a3), "r"(b0), "r"(b1),
          "r"(0u), "r"(0u));
}

__device__ __forceinline__ float ex2f(float x) {
    float y; asm("ex2.approx.f32 %0, %1;" : "=f"(y) : "f"(x)); return y;
}
__device__ __forceinline__ float lg2f(float x) {
    float y; asm("lg2.approx.f32 %0, %1;" : "=f"(y) : "f"(x)); return y;
}
__device__ __forceinline__ __half2 h2ex2(__half2 x) {
    unsigned xu = *reinterpret_cast<unsigned *>(&x), yu;
    asm("ex2.approx.f16x2 %0, %1;" : "=r"(yu) : "r"(xu));
    return *reinterpret_cast<__half2 *>(&yu);
}
__device__ __forceinline__ __half2 u2h(unsigned u) {
    return *reinterpret_cast<__half2 *>(&u);
}
__device__ __forceinline__ unsigned smem_u32(const void *p) {
    return (unsigned)__cvta_generic_to_shared(p);
}
__device__ __forceinline__ void cp16(void *sdst, const void *gsrc) {
    unsigned d = smem_u32(sdst);
    asm volatile("cp.async.cg.shared.global [%0], [%1], 16;" :: "r"(d), "l"(gsrc) : "memory");
}
#define CP_COMMIT() asm volatile("cp.async.commit_group;" ::: "memory")
#define CP_WAIT(n)  asm volatile("cp.async.wait_group %0;" :: "n"(n) : "memory")

// ---------------------------------------------------------------------------
// Stage 0: fp32 -> fp16 for x, Wq, Wk. 196608 float4, grid 768 x 256.
// ---------------------------------------------------------------------------
__global__ void __launch_bounds__(256)
prep_kernel(const float *__restrict__ x, const float *__restrict__ Wq,
            const float *__restrict__ Wk) {
    int idx = blockIdx.x * 256 + threadIdx.x;   // 0..196607
    if (idx == 0) g_done = 0;
    float4 v;
    uint2 *dst;
    if (idx < 65536) {
        v = reinterpret_cast<const float4 *>(x)[idx];
        dst = reinterpret_cast<uint2 *>(g_x16) + idx;
    } else if (idx < 131072) {
        v = reinterpret_cast<const float4 *>(Wq)[idx - 65536];
        dst = reinterpret_cast<uint2 *>(g_W16) + (idx - 65536);
    } else {
        v = reinterpret_cast<const float4 *>(Wk)[idx - 131072];
        dst = reinterpret_cast<uint2 *>(g_W16) + (idx - 65536);
    }
    __half2 h0 = __floats2half2_rn(v.x, v.y);
    __half2 h1 = __floats2half2_rn(v.z, v.w);
    uint2 u;
    u.x = *reinterpret_cast<unsigned *>(&h0);
    u.y = *reinterpret_cast<unsigned *>(&h1);
    *dst = u;
}

// ---------------------------------------------------------------------------
// Stage 1: projection. grid (16 n-tiles, 32 heads, 2 {Q,K}), 256 threads.
// C[128n x 64z] = x16_tile[128x128] @ W16[h]^T, f16 in / f32 acc.
// smem 48KB dynamic: sX 32KB + sW 16KB, XOR swizzle, cp.async loads.
// ---------------------------------------------------------------------------
__global__ void __launch_bounds__(256)
proj_kernel() {
    extern __shared__ uint4 smem[];
    uint4 *sX4 = smem;              // 128 rows x 16 chunks(16B)
    uint4 *sW4 = smem + 128 * 16;   // 64 rows x 16 chunks

    const int tid = threadIdx.x, lane = tid & 31, w = tid >> 5;
    const int nb = blockIdx.x * 128, h = blockIdx.y, isK = blockIdx.z;
    const __half *X = g_x16 + (size_t)nb * DIM;
    const __half *W = g_W16 + (size_t)isK * NH * ZD * DIM + (size_t)h * ZD * DIM;
    __half *gout = (isK ? g_K : g_Q) + ((size_t)h * NTOK + nb) * ZD;

    for (int i = tid; i < 2048; i += 256) {          // x tile
        int row = i >> 4, c = i & 15;
        cp16(&sX4[row * 16 + (c ^ (row & 7))], X + (size_t)row * DIM + c * 8);
    }
    for (int i = tid; i < 1024; i += 256) {          // W tile
        int row = i >> 4, c = i & 15;
        cp16(&sW4[row * 16 + (c ^ (row & 7))], W + (size_t)row * DIM + c * 8);
    }
    CP_COMMIT();
    CP_WAIT(0);
    __syncthreads();

    const int wm = w >> 1, wn = w & 1;
    float acc[2][4][4];
#pragma unroll
    for (int i = 0; i < 2; i++)
#pragma unroll
        for (int j = 0; j < 4; j++)
#pragma unroll
            for (int k = 0; k < 4; k++) acc[i][j][k] = 0.f;

    unsigned sXb = smem_u32(sX4), sWb = smem_u32(sW4);
    const int arow0 = wm * 32 + (lane & 15);
    const int brow_off = (lane & 7) + ((lane >> 4) & 1) * 8;
    const int bco = (lane >> 3) & 1;

#pragma unroll
    for (int kk = 0; kk < 8; kk++) {   // K = 128
        unsigned a[2][4];
#pragma unroll
        for (int i = 0; i < 2; i++) {
            int r = arow0 + i * 16;
            int ch = (kk * 2 + (lane >> 4)) ^ (r & 7);
            ldsm4(sXb + (unsigned)((r * 16 + ch) * 16), a[i][0], a[i][1], a[i][2], a[i][3]);
        }
#pragma unroll
        for (int g = 0; g < 2; g++) {
            int brow = wn * 32 + g * 16 + brow_off;
            int bch = (kk * 2 + bco) ^ (brow & 7);
            unsigned b0, b1, b2, b3;
            ldsm4(sWb + (unsigned)((brow * 16 + bch) * 16), b0, b1, b2, b3);
#pragma unroll
            for (int i = 0; i < 2; i++) {
                mma_f16_f32(acc[i][g * 2],     a[i][0], a[i][1], a[i][2], a[i][3], b0, b1);
                mma_f16_f32(acc[i][g * 2 + 1], a[i][0], a[i][1], a[i][2], a[i][3], b2, b3);
            }
        }
    }

#pragma unroll
    for (int i = 0; i < 2; i++) {
        int r = wm * 32 + i * 16 + (lane >> 2);
#pragma unroll
        for (int j = 0; j < 4; j++) {
            int cb = wn * 32 + j * 8 + 2 * (lane & 3);
            __half2 lo = __floats2half2_rn(acc[i][j][0] * QK_SCALE, acc[i][j][1] * QK_SCALE);
            __half2 hi = __floats2half2_rn(acc[i][j][2] * QK_SCALE, acc[i][j][3] * QK_SCALE);
            *reinterpret_cast<__half2 *>(gout + (size_t)r * ZD + cb) = lo;
            *reinterpret_cast<__half2 *>(gout + (size_t)(r + 8) * ZD + cb) = hi;
        }
    }
}

// ---------------------------------------------------------------------------
// Stage 2 epilogue: online (m, s) update from one f16-acc bank.
// bank[i][j][hh]: i = 16-row block, j = n-tile col pair, hh = row offset 0/+8.
// Each (i,hh) slice = 16 scores of ONE q row.
// ---------------------------------------------------------------------------
__device__ __forceinline__ void epi_bank(unsigned (&bank)[2][8][2],
                                         float *m, float *s) {
#pragma unroll
    for (int i = 0; i < 2; i++) {
#pragma unroll
        for (int hh = 0; hh < 2; hh++) {
            const int idx = i * 2 + hh;
            __half2 hv[8];
#pragma unroll
            for (int j = 0; j < 8; j++) hv[j] = u2h(bank[i][j][hh]);
            __half2 mx0 = __hmax2(hv[0], hv[4]);
            __half2 mx1 = __hmax2(hv[1], hv[5]);
            __half2 mx2 = __hmax2(hv[2], hv[6]);
            __half2 mx3 = __hmax2(hv[3], hv[7]);
            mx0 = __hmax2(__hmax2(mx0, mx1), __hmax2(mx2, mx3));
            float tmax = fmaxf(__low2float(mx0), __high2float(mx0));

            float mn = fmaxf(m[idx], tmax);
            s[idx] *= ex2f(m[idx] - mn);
            m[idx] = mn;
            __half2 mn2 = __float2half2_rn(mn);
            __half2 a0 = h2ex2(__hsub2(hv[0], mn2));
            __half2 a1 = h2ex2(__hsub2(hv[1], mn2));
            __half2 a2 = h2ex2(__hsub2(hv[2], mn2));
            __half2 a3 = h2ex2(__hsub2(hv[3], mn2));
            a0 = __hadd2(a0, h2ex2(__hsub2(hv[4], mn2)));
            a1 = __hadd2(a1, h2ex2(__hsub2(hv[5], mn2)));
            a2 = __hadd2(a2, h2ex2(__hsub2(hv[6], mn2)));
            a3 = __hadd2(a3, h2ex2(__hsub2(hv[7], mn2)));
            a0 = __hadd2(__hadd2(a0, a1), __hadd2(a2, a3));
            s[idx] += __low2float(a0) + __high2float(a0);
        }
    }
}

// ---------------------------------------------------------------------------
// Stage 2: fused scores + online base-2 lse + last-CTA final reduction.
// grid (16 q-tiles, 32 heads), 256 threads (8 warps), 4 CTAs/SM target
// (592 slots >= 512 CTAs -> single wave).
// warp w: rows 32*(w&3)..+31, col half (w>>2)*64..+63. f16 accumulators.
// Q fragments streamed per k-chunk from the persistent sQ tile (8 live regs).
// smem (dynamic 48KB): sQ 16KB + sK double-buffer 2x16KB. R7 loop schedule:
//   iter kt: [MMA+EPI on buf kt&1][sync][issue K(kt+2)][wait K(kt+1)][sync]
// ---------------------------------------------------------------------------
__global__ void __launch_bounds__(256, 4)
attn_lse_kernel(float *__restrict__ out) {
    extern __shared__ uint4 dynsmem[];
    uint4 *sQ4 = dynsmem;            // 128 rows x 8 chunks(16B), swizzled
    uint4 *sK4 = dynsmem + 128 * 8;  // 2 x (128 x 8)
    __shared__ float sM[8][4][8];    // [warp][slice][quad-row]
    __shared__ float sS[8][4][8];
    __shared__ float warpSum[4];
    __shared__ float red[256];
    __shared__ bool amLast;

    const int tid = threadIdx.x, lane = tid & 31, w = tid >> 5;
    const int wr = w & 3, wc = w >> 2;
    const int h = blockIdx.y, qt = blockIdx.x;
    const __half *gq = g_Q + ((size_t)h * NTOK + (size_t)qt * 128) * ZD;
    const __half *gk = g_K + (size_t)h * NTOK * ZD;

    // group 0: Q + K0 ; group 1: K1
    for (int i = tid; i < 1024; i += 256) {
        int row = i >> 3, c = i & 7;
        cp16(&sQ4[row * 8 + (c ^ (row & 7))], gq + (size_t)row * ZD + c * 8);
    }
    for (int i = tid; i < 1024; i += 256) {
        int row = i >> 3, c = i & 7;
        cp16(&sK4[row * 8 + (c ^ (row & 7))], gk + (size_t)row * ZD + c * 8);
    }
    CP_COMMIT();
    {
        const __half *gk1 = gk + (size_t)128 * ZD;
        uint4 *buf = sK4 + 1024;
        for (int i = tid; i < 1024; i += 256) {
            int row = i >> 3, c = i & 7;
            cp16(&buf[row * 8 + (c ^ (row & 7))], gk1 + (size_t)row * ZD + c * 8);
        }
        CP_COMMIT();
    }
    CP_WAIT(1);          // Q + K0 ready
    __syncthreads();

    const unsigned sQb = smem_u32(sQ4);

    float m[4], s[4];
#pragma unroll
    for (int i = 0; i < 4; i++) { m[i] = -INFINITY; s[i] = 0.f; }

    unsigned bank[2][8][2];

    const int brow_off = wc * 64 + (lane & 7) + ((lane >> 4) & 1) * 8;
    const int bco = (lane >> 3) & 1;
    const int qrow0 = 32 * wr + (lane & 15);
    const int qch_sel = (lane >> 4);

#pragma unroll 1
    for (int kt = 0; kt < 16; kt++) {
        const unsigned sKb = smem_u32(sK4 + (kt & 1) * 1024);

        // ---- MMA(tile kt): stream Q frags per kk; kk=0 zero-init ----
#pragma unroll
        for (int kk = 0; kk < 4; kk++) {
            unsigned a[2][4];
#pragma unroll
            for (int i = 0; i < 2; i++) {
                int r = qrow0 + 16 * i;
                int ch = (kk * 2 + qch_sel) ^ (r & 7);
                ldsm4(sQb + (unsigned)((r * 8 + ch) * 16),
                      a[i][0], a[i][1], a[i][2], a[i][3]);
            }
#pragma unroll
            for (int n16 = 0; n16 < 4; n16++) {
                int brow = n16 * 16 + brow_off;
                int bch = (kk * 2 + bco) ^ (brow & 7);
                unsigned b0, b1, b2, b3;
                ldsm4(sKb + (unsigned)((brow * 8 + bch) * 16), b0, b1, b2, b3);
                if (kk == 0) {
#pragma unroll
                    for (int i = 0; i < 2; i++) {
                        mma_f16_f16_z(bank[i][n16 * 2][0],     bank[i][n16 * 2][1],
                                      a[i][0], a[i][1], a[i][2], a[i][3], b0, b1);
                        mma_f16_f16_z(bank[i][n16 * 2 + 1][0], bank[i][n16 * 2 + 1][1],
                                      a[i][0], a[i][1], a[i][2], a[i][3], b2, b3);
                    }
                } else {
#pragma unroll
                    for (int i = 0; i < 2; i++) {
                        mma_f16_f16(bank[i][n16 * 2][0],     bank[i][n16 * 2][1],
                                    a[i][0], a[i][1], a[i][2], a[i][3], b0, b1);
                        mma_f16_f16(bank[i][n16 * 2 + 1][0], bank[i][n16 * 2 + 1][1],
                                    a[i][0], a[i][1], a[i][2], a[i][3], b2, b3);
                    }
                }
            }
        }
        epi_bank(bank, m, s);

        __syncthreads();   // all warps done reading buf[kt&1]

        if (kt + 2 < 16) {
            const __half *gkt = gk + (size_t)(kt + 2) * 128 * ZD;
            uint4 *buf = sK4 + (kt & 1) * 1024;
            for (int i = tid; i < 1024; i += 256) {
                int row = i >> 3, c = i & 7;
                cp16(&buf[row * 8 + (c ^ (row & 7))], gkt + (size_t)row * ZD + c * 8);
            }
            CP_COMMIT();
            CP_WAIT(1);    // K(kt+1) done (FIFO)
        } else if (kt + 1 < 16) {
            CP_WAIT(0);    // drain K15
        }
        __syncthreads();
    }

    // merge (m,s) across the 4 lanes of each quad (slice = 64-col half row)
#pragma unroll
    for (int idx = 0; idx < 4; idx++) {
        float mm = m[idx], ss = s[idx];
#pragma unroll
        for (int off = 1; off <= 2; off <<= 1) {
            float mo = __shfl_xor_sync(0xffffffffu, mm, off);
            float so = __shfl_xor_sync(0xffffffffu, ss, off);
            float mn = fmaxf(mm, mo);
            ss = ss * ex2f(mm - mn) + so * ex2f(mo - mn);
            mm = mn;
        }
        m[idx] = mm; s[idx] = ss;
    }
    if ((lane & 3) == 0) {
#pragma unroll
        for (int idx = 0; idx < 4; idx++) {
            sM[w][idx][lane >> 2] = m[idx];
            sS[w][idx][lane >> 2] = s[idx];
        }
    }
    __syncthreads();

    // warps 0-3: merge col-half partner (w+4), per-row lse, warp-sum
    float contrib = 0.f;
    if (wc == 0 && (lane & 3) == 0) {
#pragma unroll
        for (int idx = 0; idx < 4; idx++) {
            float ma = sM[w][idx][lane >> 2], sa = sS[w][idx][lane >> 2];
            float mb = sM[w + 4][idx][lane >> 2], sb = sS[w + 4][idx][lane >> 2];
            float mn = fmaxf(ma, mb);
            float ss = sa * ex2f(ma - mn) + sb * ex2f(mb - mn);
            contrib += mn + lg2f(ss);
        }
    }
    if (wc == 0) {
#pragma unroll
        for (int off = 16; off; off >>= 1)
            contrib += __shfl_xor_sync(0xffffffffu, contrib, off);
        if (lane == 0) warpSum[wr] = contrib;
    }
    __syncthreads();

    // publish partial, then the last CTA to finish reduces everything
    if (tid == 0) {
        g_partial[blockIdx.y * 16 + blockIdx.x] =
            warpSum[0] + warpSum[1] + warpSum[2] + warpSum[3];
        __threadfence();
        unsigned prev = atomicAdd(&g_done, 1u);
        amLast = (prev == 16u * NH - 1u);
    }
    __syncthreads();

    if (amLast) {
        __threadfence();   // make all g_partial writes visible
        red[tid] = g_partial[tid] + g_partial[tid + 256];
        __syncthreads();
        for (int st = 128; st > 0; st >>= 1) {
            if (tid < st) red[tid] += red[tid + st];
            __syncthreads();
        }
        if (tid == 0) {
            const double C = -(11.313708498984760390 * 0.69314718055994530942);
            out[0] = (float)(C * (double)red[0]);
        }
    }
}

// ---------------------------------------------------------------------------
extern "C" void kernel_launch(void *const *d_in, const int *in_sizes, int n_in,
                              void *d_out, int out_size) {
    (void)in_sizes; (void)n_in; (void)out_size;
    const float *x  = (const float *)d_in[0];
    const float *Wq = (const float *)d_in[1];
    const float *Wk = (const float *)d_in[2];
    float *out = (float *)d_out;

    static bool attr_set = false;
    if (!attr_set) {
        cudaFuncSetAttribute(proj_kernel, cudaFuncAttributeMaxDynamicSharedMemorySize, 49152);
        cudaFuncSetAttribute(attn_lse_kernel, cudaFuncAttributeMaxDynamicSharedMemorySize, 49152);
        attr_set = true;
    }

    prep_kernel<<<768, 256>>>(x, Wq, Wk);
    proj_kernel<<<dim3(16, 32, 2), 256, 49152>>>();
    attn_lse_kernel<<<dim3(16, 32), 256, 49152>>>(out);
}

// round 16
// speedup vs baseline: 1.0488x; 1.0488x over previous
#include <cuda_runtime.h>
#include <cuda_bf16.h>
#include <cuda_fp16.h>

// ---------------------------------------------------------------------------
// SelfAttention_50500225466674
// out = -(1/beta) * sum_{h,q} logsumexp_k( beta * (x Wq^T)[q,h,:] . (x Wk^T)[k,h,:] )
// N=2048, D=128, H=32, Z=64, beta = 1/sqrt(128)
// Stage 0: fp32 -> fp16 conversion of x, Wq, Wk (+ reset done-counter)
// Stage 1: fp16 HMMA projection Q and K (f32 acc), sqrt(beta*log2e) in both
// Stage 2: fused score GEMM (f16 acc, zero-init MMA) + online base-2 lse.
//          64-ROW Q TILES: grid (32,32)=1024 light CTAs, ~48 regs/thread,
//          5 CTAs/SM -> 740 slots -> 2 half-size waves (wall ~= 1x old CTA
//          time, killing the 2x full-wave quantization of R13).
//          Last-done CTA performs the final deterministic reduction.
// ---------------------------------------------------------------------------

#define NTOK 2048
#define DIM  128
#define NH   32
#define ZD   64

static __device__ __half g_x16[(size_t)NTOK * DIM];            // 0.5 MB
static __device__ __half g_W16[(size_t)2 * NH * ZD * DIM];     // 1 MB (Wq|Wk)
static __device__ __half g_Q[(size_t)NH * NTOK * ZD];          // 8 MB
static __device__ __half g_K[(size_t)NH * NTOK * ZD];          // 8 MB
static __device__ float g_partial[32 * NH];                    // 1024 partials
static __device__ unsigned g_done;                             // CTA counter

// sqrt(log2(e)/sqrt(128)) : folded into both Q and K
#define QK_SCALE 0.3570959f

// ---------------- PTX helpers ----------------
__device__ __forceinline__ void ldsm4(unsigned addr, unsigned &r0, unsigned &r1,
                                      unsigned &r2, unsigned &r3) {
    asm volatile("ldmatrix.sync.aligned.m8n8.x4.shared.b16 {%0,%1,%2,%3}, [%4];"
                 : "=r"(r0), "=r"(r1), "=r"(r2), "=r"(r3)
                 : "r"(addr));
}

// f16 inputs, f32 accumulators (projection)
__device__ __forceinline__ void mma_f16_f32(float *c, unsigned a0, unsigned a1,
                                            unsigned a2, unsigned a3,
                                            unsigned b0, unsigned b1) {
    asm volatile(
        "mma.sync.aligned.m16n8k16.row.col.f32.f16.f16.f32 "
        "{%0,%1,%2,%3}, {%4,%5,%6,%7}, {%8,%9}, {%0,%1,%2,%3};"
        : "+f"(c[0]), "+f"(c[1]), "+f"(c[2]), "+f"(c[3])
        : "r"(a0), "r"(a1), "r"(a2), "r"(a3), "r"(b0), "r"(b1));
}

// f16 inputs, f16 accumulators, accumulate into C=D
__device__ __forceinline__ void mma_f16_f16(unsigned &c0, unsigned &c1,
                                            unsigned a0, unsigned a1,
                                            unsigned a2, unsigned a3,
                                            unsigned b0, unsigned b1) {
    asm volatile(
        "mma.sync.aligned.m16n8k16.row.col.f16.f16.f16.f16 "
        "{%0,%1}, {%2,%3,%4,%5}, {%6,%7}, {%0,%1};"
        : "+r"(c0), "+r"(c1)
        : "r"(a0), "r"(a1), "r"(a2), "r"(a3), "r"(b0), "r"(b1));
}

// f16 inputs, f16 accumulators, C = 0 (fresh init, no bank zeroing)
__device__ __forceinline__ void mma_f16_f16_z(unsigned &c0, unsigned &c1,
                                              unsigned a0, unsigned a1,
                                              unsigned a2, unsigned a3,
                                              unsigned b0, unsigned b1) {
    asm volatile(
        "mma.sync.aligned.m16n8k16.row.col.f16.f16.f16.f16 "
        "{%0,%1}, {%2,%3,%4,%5}, {%6,%7}, {%8,%9};"
        : "=r"(c0), "=r"(c1)
        : "r"(a0), "r"(a1), "r"(a2), "r"(a3), "r"(b0), "r"(b1),
          "r"(0u), "r"(0u));
}

__device__ __forceinline__ float ex2f(float x) {
    float y; asm("ex2.approx.f32 %0, %1;" : "=f"(y) : "f"(x)); return y;
}
__device__ __forceinline__ float lg2f(float x) {
    float y; asm("lg2.approx.f32 %0, %1;" : "=f"(y) : "f"(x)); return y;
}
__device__ __forceinline__ __half2 h2ex2(__half2 x) {
    unsigned xu = *reinterpret_cast<unsigned *>(&x), yu;
    asm("ex2.approx.f16x2 %0, %1;" : "=r"(yu) : "r"(xu));
    return *reinterpret_cast<__half2 *>(&yu);
}
__device__ __forceinline__ __half2 u2h(unsigned u) {
    return *reinterpret_cast<__half2 *>(&u);
}
__device__ __forceinline__ unsigned smem_u32(const void *p) {
    return (unsigned)__cvta_generic_to_shared(p);
}
__device__ __forceinline__ void cp16(void *sdst, const void *gsrc) {
    unsigned d = smem_u32(sdst);
    asm volatile("cp.async.cg.shared.global [%0], [%1], 16;" :: "r"(d), "l"(gsrc) : "memory");
}
#define CP_COMMIT() asm volatile("cp.async.commit_group;" ::: "memory")
#define CP_WAIT(n)  asm volatile("cp.async.wait_group %0;" :: "n"(n) : "memory")

// ---------------------------------------------------------------------------
// Stage 0: fp32 -> fp16 for x, Wq, Wk. 196608 float4, grid 768 x 256.
// ---------------------------------------------------------------------------
__global__ void __launch_bounds__(256)
prep_kernel(const float *__restrict__ x, const float *__restrict__ Wq,
            const float *__restrict__ Wk) {
    int idx = blockIdx.x * 256 + threadIdx.x;   // 0..196607
    if (idx == 0) g_done = 0;
    float4 v;
    uint2 *dst;
    if (idx < 65536) {
        v = reinterpret_cast<const float4 *>(x)[idx];
        dst = reinterpret_cast<uint2 *>(g_x16) + idx;
    } else if (idx < 131072) {
        v = reinterpret_cast<const float4 *>(Wq)[idx - 65536];
        dst = reinterpret_cast<uint2 *>(g_W16) + (idx - 65536);
    } else {
        v = reinterpret_cast<const float4 *>(Wk)[idx - 131072];
        dst = reinterpret_cast<uint2 *>(g_W16) + (idx - 65536);
    }
    __half2 h0 = __floats2half2_rn(v.x, v.y);
    __half2 h1 = __floats2half2_rn(v.z, v.w);
    uint2 u;
    u.x = *reinterpret_cast<unsigned *>(&h0);
    u.y = *reinterpret_cast<unsigned *>(&h1);
    *dst = u;
}

// ---------------------------------------------------------------------------
// Stage 1: projection. grid (16 n-tiles, 32 heads, 2 {Q,K}), 256 threads.
// C[128n x 64z] = x16_tile[128x128] @ W16[h]^T, f16 in / f32 acc.
// smem 48KB dynamic: sX 32KB + sW 16KB, XOR swizzle, cp.async loads.
// ---------------------------------------------------------------------------
__global__ void __launch_bounds__(256)
proj_kernel() {
    extern __shared__ uint4 smem[];
    uint4 *sX4 = smem;              // 128 rows x 16 chunks(16B)
    uint4 *sW4 = smem + 128 * 16;   // 64 rows x 16 chunks

    const int tid = threadIdx.x, lane = tid & 31, w = tid >> 5;
    const int nb = blockIdx.x * 128, h = blockIdx.y, isK = blockIdx.z;
    const __half *X = g_x16 + (size_t)nb * DIM;
    const __half *W = g_W16 + (size_t)isK * NH * ZD * DIM + (size_t)h * ZD * DIM;
    __half *gout = (isK ? g_K : g_Q) + ((size_t)h * NTOK + nb) * ZD;

    for (int i = tid; i < 2048; i += 256) {          // x tile
        int row = i >> 4, c = i & 15;
        cp16(&sX4[row * 16 + (c ^ (row & 7))], X + (size_t)row * DIM + c * 8);
    }
    for (int i = tid; i < 1024; i += 256) {          // W tile
        int row = i >> 4, c = i & 15;
        cp16(&sW4[row * 16 + (c ^ (row & 7))], W + (size_t)row * DIM + c * 8);
    }
    CP_COMMIT();
    CP_WAIT(0);
    __syncthreads();

    const int wm = w >> 1, wn = w & 1;
    float acc[2][4][4];
#pragma unroll
    for (int i = 0; i < 2; i++)
#pragma unroll
        for (int j = 0; j < 4; j++)
#pragma unroll
            for (int k = 0; k < 4; k++) acc[i][j][k] = 0.f;

    unsigned sXb = smem_u32(sX4), sWb = smem_u32(sW4);
    const int arow0 = wm * 32 + (lane & 15);
    const int brow_off = (lane & 7) + ((lane >> 4) & 1) * 8;
    const int bco = (lane >> 3) & 1;

#pragma unroll
    for (int kk = 0; kk < 8; kk++) {   // K = 128
        unsigned a[2][4];
#pragma unroll
        for (int i = 0; i < 2; i++) {
            int r = arow0 + i * 16;
            int ch = (kk * 2 + (lane >> 4)) ^ (r & 7);
            ldsm4(sXb + (unsigned)((r * 16 + ch) * 16), a[i][0], a[i][1], a[i][2], a[i][3]);
        }
#pragma unroll
        for (int g = 0; g < 2; g++) {
            int brow = wn * 32 + g * 16 + brow_off;
            int bch = (kk * 2 + bco) ^ (brow & 7);
            unsigned b0, b1, b2, b3;
            ldsm4(sWb + (unsigned)((brow * 16 + bch) * 16), b0, b1, b2, b3);
#pragma unroll
            for (int i = 0; i < 2; i++) {
                mma_f16_f32(acc[i][g * 2],     a[i][0], a[i][1], a[i][2], a[i][3], b0, b1);
                mma_f16_f32(acc[i][g * 2 + 1], a[i][0], a[i][1], a[i][2], a[i][3], b2, b3);
            }
        }
    }

#pragma unroll
    for (int i = 0; i < 2; i++) {
        int r = wm * 32 + i * 16 + (lane >> 2);
#pragma unroll
        for (int j = 0; j < 4; j++) {
            int cb = wn * 32 + j * 8 + 2 * (lane & 3);
            __half2 lo = __floats2half2_rn(acc[i][j][0] * QK_SCALE, acc[i][j][1] * QK_SCALE);
            __half2 hi = __floats2half2_rn(acc[i][j][2] * QK_SCALE, acc[i][j][3] * QK_SCALE);
            *reinterpret_cast<__half2 *>(gout + (size_t)r * ZD + cb) = lo;
            *reinterpret_cast<__half2 *>(gout + (size_t)(r + 8) * ZD + cb) = hi;
        }
    }
}

// ---------------------------------------------------------------------------
// Stage 2 epilogue: online (m, s) update from one f16-acc bank (64-row tile).
// bank[j][hh]: j = n-tile col pair, hh = row offset 0/+8.
// Each hh slice = 16 scores of ONE q row.
// ---------------------------------------------------------------------------
__device__ __forceinline__ void epi_bank(unsigned (&bank)[8][2],
                                         float *m, float *s) {
#pragma unroll
    for (int hh = 0; hh < 2; hh++) {
        __half2 hv[8];
#pragma unroll
        for (int j = 0; j < 8; j++) hv[j] = u2h(bank[j][hh]);
        __half2 mx0 = __hmax2(hv[0], hv[4]);
        __half2 mx1 = __hmax2(hv[1], hv[5]);
        __half2 mx2 = __hmax2(hv[2], hv[6]);
        __half2 mx3 = __hmax2(hv[3], hv[7]);
        mx0 = __hmax2(__hmax2(mx0, mx1), __hmax2(mx2, mx3));
        float tmax = fmaxf(__low2float(mx0), __high2float(mx0));

        float mn = fmaxf(m[hh], tmax);
        s[hh] *= ex2f(m[hh] - mn);
        m[hh] = mn;
        __half2 mn2 = __float2half2_rn(mn);
        __half2 a0 = h2ex2(__hsub2(hv[0], mn2));
        __half2 a1 = h2ex2(__hsub2(hv[1], mn2));
        __half2 a2 = h2ex2(__hsub2(hv[2], mn2));
        __half2 a3 = h2ex2(__hsub2(hv[3], mn2));
        a0 = __hadd2(a0, h2ex2(__hsub2(hv[4], mn2)));
        a1 = __hadd2(a1, h2ex2(__hsub2(hv[5], mn2)));
        a2 = __hadd2(a2, h2ex2(__hsub2(hv[6], mn2)));
        a3 = __hadd2(a3, h2ex2(__hsub2(hv[7], mn2)));
        a0 = __hadd2(__hadd2(a0, a1), __hadd2(a2, a3));
        s[hh] += __low2float(a0) + __high2float(a0);
    }
}

// ---------------------------------------------------------------------------
// Stage 2: fused scores + online base-2 lse + last-CTA final reduction.
// grid (32 q-tiles of 64 rows, 32 heads) = 1024 CTAs, 256 threads (8 warps),
// 5 CTAs/SM target (740 slots -> 2 half-size waves).
// warp w: rows 16*(w&3)..+15, col half (w>>2)*64..+63. f16 accumulators.
// Q fragments streamed per k-chunk from the persistent sQ tile.
// smem (dynamic 40KB): sQ 8KB + sK double-buffer 2x16KB. R7 loop schedule:
//   iter kt: [MMA+EPI on buf kt&1][sync][issue K(kt+2)][wait K(kt+1)][sync]
// ---------------------------------------------------------------------------
__global__ void __launch_bounds__(256, 5)
attn_lse_kernel(float *__restrict__ out) {
    extern __shared__ uint4 dynsmem[];
    uint4 *sQ4 = dynsmem;            // 64 rows x 8 chunks(16B), swizzled
    uint4 *sK4 = dynsmem + 64 * 8;   // 2 x (128 x 8)
    __shared__ float sM[8][2][8];    // [warp][slice][quad-row]
    __shared__ float sS[8][2][8];
    __shared__ float warpSum[4];
    __shared__ float red[256];
    __shared__ bool amLast;

    const int tid = threadIdx.x, lane = tid & 31, w = tid >> 5;
    const int wr = w & 3, wc = w >> 2;
    const int h = blockIdx.y, qt = blockIdx.x;
    const __half *gq = g_Q + ((size_t)h * NTOK + (size_t)qt * 64) * ZD;
    const __half *gk = g_K + (size_t)h * NTOK * ZD;

    // group 0: Q + K0 ; group 1: K1
    for (int i = tid; i < 512; i += 256) {
        int row = i >> 3, c = i & 7;
        cp16(&sQ4[row * 8 + (c ^ (row & 7))], gq + (size_t)row * ZD + c * 8);
    }
    for (int i = tid; i < 1024; i += 256) {
        int row = i >> 3, c = i & 7;
        cp16(&sK4[row * 8 + (c ^ (row & 7))], gk + (size_t)row * ZD + c * 8);
    }
    CP_COMMIT();
    {
        const __half *gk1 = gk + (size_t)128 * ZD;
        uint4 *buf = sK4 + 1024;
        for (int i = tid; i < 1024; i += 256) {
            int row = i >> 3, c = i & 7;
            cp16(&buf[row * 8 + (c ^ (row & 7))], gk1 + (size_t)row * ZD + c * 8);
        }
        CP_COMMIT();
    }
    CP_WAIT(1);          // Q + K0 ready
    __syncthreads();

    const unsigned sQb = smem_u32(sQ4);

    float m[2], s[2];
    m[0] = -INFINITY; s[0] = 0.f; m[1] = -INFINITY; s[1] = 0.f;

    unsigned bank[8][2];

    const int brow_off = wc * 64 + (lane & 7) + ((lane >> 4) & 1) * 8;
    const int bco = (lane >> 3) & 1;
    const int qrow0 = 16 * wr + (lane & 15);
    const int qch_sel = (lane >> 4);

#pragma unroll 1
    for (int kt = 0; kt < 16; kt++) {
        const unsigned sKb = smem_u32(sK4 + (kt & 1) * 1024);

        // ---- MMA(tile kt): stream Q frag per kk; kk=0 zero-init ----
#pragma unroll
        for (int kk = 0; kk < 4; kk++) {
            unsigned a0, a1, a2, a3;
            {
                int ch = (kk * 2 + qch_sel) ^ (qrow0 & 7);
                ldsm4(sQb + (unsigned)((qrow0 * 8 + ch) * 16), a0, a1, a2, a3);
            }
#pragma unroll
            for (int n16 = 0; n16 < 4; n16++) {
                int brow = n16 * 16 + brow_off;
                int bch = (kk * 2 + bco) ^ (brow & 7);
                unsigned b0, b1, b2, b3;
                ldsm4(sKb + (unsigned)((brow * 8 + bch) * 16), b0, b1, b2, b3);
                if (kk == 0) {
                    mma_f16_f16_z(bank[n16 * 2][0],     bank[n16 * 2][1],
                                  a0, a1, a2, a3, b0, b1);
                    mma_f16_f16_z(bank[n16 * 2 + 1][0], bank[n16 * 2 + 1][1],
                                  a0, a1, a2, a3, b2, b3);
                } else {
                    mma_f16_f16(bank[n16 * 2][0],     bank[n16 * 2][1],
                                a0, a1, a2, a3, b0, b1);
                    mma_f16_f16(bank[n16 * 2 + 1][0], bank[n16 * 2 + 1][1],
                                a0, a1, a2, a3, b2, b3);
                }
            }
        }
        epi_bank(bank, m, s);

        __syncthreads();   // all warps done reading buf[kt&1]

        if (kt + 2 < 16) {
            const __half *gkt = gk + (size_t)(kt + 2) * 128 * ZD;
            uint4 *buf = sK4 + (kt & 1) * 1024;
            for (int i = tid; i < 1024; i += 256) {
                int row = i >> 3, c = i & 7;
                cp16(&buf[row * 8 + (c ^ (row & 7))], gkt + (size_t)row * ZD + c * 8);
            }
            CP_COMMIT();
            CP_WAIT(1);    // K(kt+1) done (FIFO)
        } else if (kt + 1 < 16) {
            CP_WAIT(0);    // drain K15
        }
        __syncthreads();
    }

    // merge (m,s) across the 4 lanes of each quad (slice = 64-col half row)
#pragma unroll
    for (int idx = 0; idx < 2; idx++) {
        float mm = m[idx], ss = s[idx];
#pragma unroll
        for (int off = 1; off <= 2; off <<= 1) {
            float mo = __shfl_xor_sync(0xffffffffu, mm, off);
            float so = __shfl_xor_sync(0xffffffffu, ss, off);
            float mn = fmaxf(mm, mo);
            ss = ss * ex2f(mm - mn) + so * ex2f(mo - mn);
            mm = mn;
        }
        m[idx] = mm; s[idx] = ss;
    }
    if ((lane & 3) == 0) {
#pragma unroll
        for (int idx = 0; idx < 2; idx++) {
            sM[w][idx][lane >> 2] = m[idx];
            sS[w][idx][lane >> 2] = s[idx];
        }
    }
    __syncthreads();

    // warps 0-3: merge col-half partner (w+4), per-row lse, warp-sum
    float contrib = 0.f;
    if (wc == 0 && (lane & 3) == 0) {
#pragma unroll
        for (int idx = 0; idx < 2; idx++) {
            float ma = sM[w][idx][lane >> 2], sa = sS[w][idx][lane >> 2];
            float mb = sM[w + 4][idx][lane >> 2], sb = sS[w + 4][idx][lane >> 2];
            float mn = fmaxf(ma, mb);
            float ss = sa * ex2f(ma - mn) + sb * ex2f(mb - mn);
            contrib += mn + lg2f(ss);
        }
    }
    if (wc == 0) {
#pragma unroll
        for (int off = 16; off; off >>= 1)
            contrib += __shfl_xor_sync(0xffffffffu, contrib, off);
        if (lane == 0) warpSum[wr] = contrib;
    }
    __syncthreads();

    // publish partial, then the last CTA to finish reduces everything
    if (tid == 0) {
        g_partial[blockIdx.y * 32 + blockIdx.x] =
            warpSum[0] + warpSum[1] + warpSum[2] + warpSum[3];
        __threadfence();
        unsigned prev = atomicAdd(&g_done, 1u);
        amLast = (prev == 32u * NH - 1u);
    }
    __syncthreads();

    if (amLast) {
        __threadfence();   // make all g_partial writes visible
        red[tid] = (g_partial[tid]       + g_partial[tid + 256]) +
                   (g_partial[tid + 512] + g_partial[tid + 768]);
        __syncthreads();
        for (int st = 128; st > 0; st >>= 1) {
            if (tid < st) red[tid] += red[tid + st];
            __syncthreads();
        }
        if (tid == 0) {
            const double C = -(11.313708498984760390 * 0.69314718055994530942);
            out[0] = (float)(C * (double)red[0]);
        }
    }
}

// ---------------------------------------------------------------------------
extern "C" void kernel_launch(void *const *d_in, const int *in_sizes, int n_in,
                              void *d_out, int out_size) {
    (void)in_sizes; (void)n_in; (void)out_size;
    const float *x  = (const float *)d_in[0];
    const float *Wq = (const float *)d_in[1];
    const float *Wk = (const float *)d_in[2];
    float *out = (float *)d_out;

    static bool attr_set = false;
    if (!attr_set) {
        cudaFuncSetAttribute(proj_kernel, cudaFuncAttributeMaxDynamicSharedMemorySize, 49152);
        cudaFuncSetAttribute(attn_lse_kernel, cudaFuncAttributeMaxDynamicSharedMemorySize, 40960);
        attr_set = true;
    }

    prep_kernel<<<768, 256>>>(x, Wq, Wk);
    proj_kernel<<<dim3(16, 32, 2), 256, 49152>>>();
    attn_lse_kernel<<<dim3(32, 32), 256, 40960>>>(out);
}

// round 17
// speedup vs baseline: 1.0712x; 1.0214x over previous
#include <cuda_runtime.h>
#include <cuda_bf16.h>
#include <cuda_fp16.h>

// ---------------------------------------------------------------------------
// SelfAttention_50500225466674
// out = -(1/beta) * sum_{h,q} logsumexp_k( beta * (x Wq^T)[q,h,:] . (x Wk^T)[k,h,:] )
// N=2048, D=128, H=32, Z=64, beta = 1/sqrt(128)
// Stage 0: fp32 -> fp16 conversion of x, Wq, Wk (+ reset done-counter)
// Stage 1: K projection ONLY (fp16 HMMA, f32 acc), sqrt(beta*log2e) folded in
// Stage 2: attn computes its own 64x64 Q tile in a smem-resident prologue
//          (stages x+Wq in the K ring space, HMMA f32 acc, scale, store f16
//          to sQ -- accumulators die before the mainloop, unlike R10), then
//          fused score GEMM (f16 acc, zero-init MMA) + online base-2 lse.
//          64-row Q tiles, 1024 light CTAs, 5 CTAs/SM.
//          Last-done CTA performs the final deterministic reduction.
// ---------------------------------------------------------------------------

#define NTOK 2048
#define DIM  128
#define NH   32
#define ZD   64

static __device__ __half g_x16[(size_t)NTOK * DIM];            // 0.5 MB
static __device__ __half g_W16[(size_t)2 * NH * ZD * DIM];     // 1 MB (Wq|Wk)
static __device__ __half g_K[(size_t)NH * NTOK * ZD];          // 8 MB
static __device__ float g_partial[32 * NH];                    // 1024 partials
static __device__ unsigned g_done;                             // CTA counter

// sqrt(log2(e)/sqrt(128)) : folded into both Q and K
#define QK_SCALE 0.3570959f

// ---------------- PTX helpers ----------------
__device__ __forceinline__ void ldsm4(unsigned addr, unsigned &r0, unsigned &r1,
                                      unsigned &r2, unsigned &r3) {
    asm volatile("ldmatrix.sync.aligned.m8n8.x4.shared.b16 {%0,%1,%2,%3}, [%4];"
                 : "=r"(r0), "=r"(r1), "=r"(r2), "=r"(r3)
                 : "r"(addr));
}

// f16 inputs, f32 accumulators (projection / Q prologue)
__device__ __forceinline__ void mma_f16_f32(float *c, unsigned a0, unsigned a1,
                                            unsigned a2, unsigned a3,
                                            unsigned b0, unsigned b1) {
    asm volatile(
        "mma.sync.aligned.m16n8k16.row.col.f32.f16.f16.f32 "
        "{%0,%1,%2,%3}, {%4,%5,%6,%7}, {%8,%9}, {%0,%1,%2,%3};"
        : "+f"(c[0]), "+f"(c[1]), "+f"(c[2]), "+f"(c[3])
        : "r"(a0), "r"(a1), "r"(a2), "r"(a3), "r"(b0), "r"(b1));
}

// f16 inputs, f16 accumulators, accumulate into C=D
__device__ __forceinline__ void mma_f16_f16(unsigned &c0, unsigned &c1,
                                            unsigned a0, unsigned a1,
                                            unsigned a2, unsigned a3,
                                            unsigned b0, unsigned b1) {
    asm volatile(
        "mma.sync.aligned.m16n8k16.row.col.f16.f16.f16.f16 "
        "{%0,%1}, {%2,%3,%4,%5}, {%6,%7}, {%0,%1};"
        : "+r"(c0), "+r"(c1)
        : "r"(a0), "r"(a1), "r"(a2), "r"(a3), "r"(b0), "r"(b1));
}

// f16 inputs, f16 accumulators, C = 0 (fresh init, no bank zeroing)
__device__ __forceinline__ void mma_f16_f16_z(unsigned &c0, unsigned &c1,
                                              unsigned a0, unsigned a1,
                                              unsigned a2, unsigned a3,
                                              unsigned b0, unsigned b1) {
    asm volatile(
        "mma.sync.aligned.m16n8k16.row.col.f16.f16.f16.f16 "
        "{%0,%1}, {%2,%3,%4,%5}, {%6,%7}, {%8,%9};"
        : "=r"(c0), "=r"(c1)
        : "r"(a0), "r"(a1), "r"(a2), "r"(a3), "r"(b0), "r"(b1),
          "r"(0u), "r"(0u));
}

__device__ __forceinline__ float ex2f(float x) {
    float y; asm("ex2.approx.f32 %0, %1;" : "=f"(y) : "f"(x)); return y;
}
__device__ __forceinline__ float lg2f(float x) {
    float y; asm("lg2.approx.f32 %0, %1;" : "=f"(y) : "f"(x)); return y;
}
__device__ __forceinline__ __half2 h2ex2(__half2 x) {
    unsigned xu = *reinterpret_cast<unsigned *>(&x), yu;
    asm("ex2.approx.f16x2 %0, %1;" : "=r"(yu) : "r"(xu));
    return *reinterpret_cast<__half2 *>(&yu);
}
__device__ __forceinline__ __half2 u2h(unsigned u) {
    return *reinterpret_cast<__half2 *>(&u);
}
__device__ __forceinline__ unsigned packh2(float a, float b) {
    __half2 h = __floats2half2_rn(a, b);
    return *reinterpret_cast<unsigned *>(&h);
}
__device__ __forceinline__ unsigned smem_u32(const void *p) {
    return (unsigned)__cvta_generic_to_shared(p);
}
__device__ __forceinline__ void sts32(unsigned addr, unsigned v) {
    asm volatile("st.shared.b32 [%0], %1;" :: "r"(addr), "r"(v) : "memory");
}
__device__ __forceinline__ void cp16(void *sdst, const void *gsrc) {
    unsigned d = smem_u32(sdst);
    asm volatile("cp.async.cg.shared.global [%0], [%1], 16;" :: "r"(d), "l"(gsrc) : "memory");
}
#define CP_COMMIT() asm volatile("cp.async.commit_group;" ::: "memory")
#define CP_WAIT(n)  asm volatile("cp.async.wait_group %0;" :: "n"(n) : "memory")

// ---------------------------------------------------------------------------
// Stage 0: fp32 -> fp16 for x, Wq, Wk. 196608 float4, grid 768 x 256.
// ---------------------------------------------------------------------------
__global__ void __launch_bounds__(256)
prep_kernel(const float *__restrict__ x, const float *__restrict__ Wq,
            const float *__restrict__ Wk) {
    int idx = blockIdx.x * 256 + threadIdx.x;   // 0..196607
    if (idx == 0) g_done = 0;
    float4 v;
    uint2 *dst;
    if (idx < 65536) {
        v = reinterpret_cast<const float4 *>(x)[idx];
        dst = reinterpret_cast<uint2 *>(g_x16) + idx;
    } else if (idx < 131072) {
        v = reinterpret_cast<const float4 *>(Wq)[idx - 65536];
        dst = reinterpret_cast<uint2 *>(g_W16) + (idx - 65536);
    } else {
        v = reinterpret_cast<const float4 *>(Wk)[idx - 131072];
        dst = reinterpret_cast<uint2 *>(g_W16) + (idx - 65536);
    }
    __half2 h0 = __floats2half2_rn(v.x, v.y);
    __half2 h1 = __floats2half2_rn(v.z, v.w);
    uint2 u;
    u.x = *reinterpret_cast<unsigned *>(&h0);
    u.y = *reinterpret_cast<unsigned *>(&h1);
    *dst = u;
}

// ---------------------------------------------------------------------------
// Stage 1: K projection only. grid (16 n-tiles, 32 heads), 256 threads.
// K[128n x 64z] = x16_tile[128x128] @ Wk16[h]^T, f16 in / f32 acc.
// smem 48KB dynamic: sX 32KB + sW 16KB, XOR swizzle, cp.async loads.
// ---------------------------------------------------------------------------
__global__ void __launch_bounds__(256)
kproj_kernel() {
    extern __shared__ uint4 smem[];
    uint4 *sX4 = smem;              // 128 rows x 16 chunks(16B)
    uint4 *sW4 = smem + 128 * 16;   // 64 rows x 16 chunks

    const int tid = threadIdx.x, lane = tid & 31, w = tid >> 5;
    const int nb = blockIdx.x * 128, h = blockIdx.y;
    const __half *X = g_x16 + (size_t)nb * DIM;
    const __half *W = g_W16 + (size_t)NH * ZD * DIM + (size_t)h * ZD * DIM;
    __half *gout = g_K + ((size_t)h * NTOK + nb) * ZD;

    for (int i = tid; i < 2048; i += 256) {          // x tile
        int row = i >> 4, c = i & 15;
        cp16(&sX4[row * 16 + (c ^ (row & 7))], X + (size_t)row * DIM + c * 8);
    }
    for (int i = tid; i < 1024; i += 256) {          // Wk tile
        int row = i >> 4, c = i & 15;
        cp16(&sW4[row * 16 + (c ^ (row & 7))], W + (size_t)row * DIM + c * 8);
    }
    CP_COMMIT();
    CP_WAIT(0);
    __syncthreads();

    const int wm = w >> 1, wn = w & 1;
    float acc[2][4][4];
#pragma unroll
    for (int i = 0; i < 2; i++)
#pragma unroll
        for (int j = 0; j < 4; j++)
#pragma unroll
            for (int k = 0; k < 4; k++) acc[i][j][k] = 0.f;

    unsigned sXb = smem_u32(sX4), sWb = smem_u32(sW4);
    const int arow0 = wm * 32 + (lane & 15);
    const int brow_off = (lane & 7) + ((lane >> 4) & 1) * 8;
    const int bco = (lane >> 3) & 1;

#pragma unroll
    for (int kk = 0; kk < 8; kk++) {   // K = 128
        unsigned a[2][4];
#pragma unroll
        for (int i = 0; i < 2; i++) {
            int r = arow0 + i * 16;
            int ch = (kk * 2 + (lane >> 4)) ^ (r & 7);
            ldsm4(sXb + (unsigned)((r * 16 + ch) * 16), a[i][0], a[i][1], a[i][2], a[i][3]);
        }
#pragma unroll
        for (int g = 0; g < 2; g++) {
            int brow = wn * 32 + g * 16 + brow_off;
            int bch = (kk * 2 + bco) ^ (brow & 7);
            unsigned b0, b1, b2, b3;
            ldsm4(sWb + (unsigned)((brow * 16 + bch) * 16), b0, b1, b2, b3);
#pragma unroll
            for (int i = 0; i < 2; i++) {
                mma_f16_f32(acc[i][g * 2],     a[i][0], a[i][1], a[i][2], a[i][3], b0, b1);
                mma_f16_f32(acc[i][g * 2 + 1], a[i][0], a[i][1], a[i][2], a[i][3], b2, b3);
            }
        }
    }

#pragma unroll
    for (int i = 0; i < 2; i++) {
        int r = wm * 32 + i * 16 + (lane >> 2);
#pragma unroll
        for (int j = 0; j < 4; j++) {
            int cb = wn * 32 + j * 8 + 2 * (lane & 3);
            __half2 lo = __floats2half2_rn(acc[i][j][0] * QK_SCALE, acc[i][j][1] * QK_SCALE);
            __half2 hi = __floats2half2_rn(acc[i][j][2] * QK_SCALE, acc[i][j][3] * QK_SCALE);
            *reinterpret_cast<__half2 *>(gout + (size_t)r * ZD + cb) = lo;
            *reinterpret_cast<__half2 *>(gout + (size_t)(r + 8) * ZD + cb) = hi;
        }
    }
}

// ---------------------------------------------------------------------------
// Stage 2 epilogue: online (m, s) update from one f16-acc bank (64-row tile).
// ---------------------------------------------------------------------------
__device__ __forceinline__ void epi_bank(unsigned (&bank)[8][2],
                                         float *m, float *s) {
#pragma unroll
    for (int hh = 0; hh < 2; hh++) {
        __half2 hv[8];
#pragma unroll
        for (int j = 0; j < 8; j++) hv[j] = u2h(bank[j][hh]);
        __half2 mx0 = __hmax2(hv[0], hv[4]);
        __half2 mx1 = __hmax2(hv[1], hv[5]);
        __half2 mx2 = __hmax2(hv[2], hv[6]);
        __half2 mx3 = __hmax2(hv[3], hv[7]);
        mx0 = __hmax2(__hmax2(mx0, mx1), __hmax2(mx2, mx3));
        float tmax = fmaxf(__low2float(mx0), __high2float(mx0));

        float mn = fmaxf(m[hh], tmax);
        s[hh] *= ex2f(m[hh] - mn);
        m[hh] = mn;
        __half2 mn2 = __float2half2_rn(mn);
        __half2 a0 = h2ex2(__hsub2(hv[0], mn2));
        __half2 a1 = h2ex2(__hsub2(hv[1], mn2));
        __half2 a2 = h2ex2(__hsub2(hv[2], mn2));
        __half2 a3 = h2ex2(__hsub2(hv[3], mn2));
        a0 = __hadd2(a0, h2ex2(__hsub2(hv[4], mn2)));
        a1 = __hadd2(a1, h2ex2(__hsub2(hv[5], mn2)));
        a2 = __hadd2(a2, h2ex2(__hsub2(hv[6], mn2)));
        a3 = __hadd2(a3, h2ex2(__hsub2(hv[7], mn2)));
        a0 = __hadd2(__hadd2(a0, a1), __hadd2(a2, a3));
        s[hh] += __low2float(a0) + __high2float(a0);
    }
}

// ---------------------------------------------------------------------------
// Stage 2: Q prologue (in-smem) + fused scores + online base-2 lse +
// last-CTA final reduction.
// grid (32 q-tiles of 64 rows, 32 heads) = 1024 CTAs, 256 threads (8 warps),
// 5 CTAs/SM target.
// Prologue: stage x(64x128)+Wq(64x128) in the K ring space, 8-warp HMMA
// Q-GEMM (f32 acc, same math/order as old proj -> bit-identical Q), store
// f16 to sQ swizzled. Accumulators die before the mainloop.
// Mainloop: warp w: rows 16*(w&3)..+15, col half (w>>2)*64..+63.
// smem (dynamic 40KB): sQ 8KB + sK double-buffer 2x16KB. R7 loop schedule.
// ---------------------------------------------------------------------------
__global__ void __launch_bounds__(256, 5)
attn_lse_kernel(float *__restrict__ out) {
    extern __shared__ uint4 dynsmem[];
    uint4 *sQ4 = dynsmem;            // 64 rows x 8 chunks(16B), swizzled
    uint4 *sK4 = dynsmem + 64 * 8;   // 2 x (128 x 8)
    __shared__ float sM[8][2][8];    // [warp][slice][quad-row]
    __shared__ float sS[8][2][8];
    __shared__ float warpSum[4];
    __shared__ float red[256];
    __shared__ bool amLast;

    const int tid = threadIdx.x, lane = tid & 31, w = tid >> 5;
    const int wr = w & 3, wc = w >> 2;
    const int h = blockIdx.y, qt = blockIdx.x;
    const __half *gk = g_K + (size_t)h * NTOK * ZD;

    // ================= Q prologue =================
    {
        // stage x tile and Wq into the (not yet used) K ring space
        uint4 *sX4 = sK4;            // 64 rows x 16 chunks (16KB)
        uint4 *sW4 = sK4 + 1024;     // 64 rows x 16 chunks (16KB)
        const __half *gx = g_x16 + (size_t)qt * 64 * DIM;
        const __half *gwq = g_W16 + (size_t)h * ZD * DIM;
        for (int i = tid; i < 1024; i += 256) {
            int row = i >> 4, c = i & 15;
            cp16(&sX4[row * 16 + (c ^ (row & 7))], gx + (size_t)row * DIM + c * 8);
        }
        for (int i = tid; i < 1024; i += 256) {
            int row = i >> 4, c = i & 15;
            cp16(&sW4[row * 16 + (c ^ (row & 7))], gwq + (size_t)row * DIM + c * 8);
        }
        CP_COMMIT();
        CP_WAIT(0);
        __syncthreads();

        // Q[64 x 64] = x @ Wq^T (f32 acc). warp w: rows 16*(w&3), cols 32*(w>>2).
        float qacc[2][2][4];
#pragma unroll
        for (int g = 0; g < 2; g++)
#pragma unroll
            for (int t = 0; t < 2; t++)
#pragma unroll
                for (int k = 0; k < 4; k++) qacc[g][t][k] = 0.f;

        const unsigned sXb = smem_u32(sX4), sWb = smem_u32(sW4);
        const int qm = 16 * wr, qn = 32 * wc;
        const int arow = qm + (lane & 15);
        const int pbrow_off = (lane & 7) + ((lane >> 4) & 1) * 8;
        const int pbco = (lane >> 3) & 1;

#pragma unroll
        for (int kk = 0; kk < 8; kk++) {   // D = 128
            unsigned a0, a1, a2, a3;
            {
                int ch = (kk * 2 + (lane >> 4)) ^ (arow & 7);
                ldsm4(sXb + (unsigned)((arow * 16 + ch) * 16), a0, a1, a2, a3);
            }
#pragma unroll
            for (int g = 0; g < 2; g++) {
                int brow = qn + g * 16 + pbrow_off;
                int bch = (kk * 2 + pbco) ^ (brow & 7);
                unsigned b0, b1, b2, b3;
                ldsm4(sWb + (unsigned)((brow * 16 + bch) * 16), b0, b1, b2, b3);
                mma_f16_f32(qacc[g][0], a0, a1, a2, a3, b0, b1);
                mma_f16_f32(qacc[g][1], a0, a1, a2, a3, b2, b3);
            }
        }

        // store Q tile to sQ (f16, K-major, swizzled: chunk = (col>>3)^(row&7))
        const unsigned sQw = smem_u32(sQ4);
        const int r0 = qm + (lane >> 2);
#pragma unroll
        for (int g = 0; g < 2; g++) {
#pragma unroll
            for (int t = 0; t < 2; t++) {
                int cb = qn + g * 16 + t * 8 + 2 * (lane & 3);
                unsigned lo = packh2(qacc[g][t][0] * QK_SCALE, qacc[g][t][1] * QK_SCALE);
                unsigned hi = packh2(qacc[g][t][2] * QK_SCALE, qacc[g][t][3] * QK_SCALE);
                int ch = cb >> 3, off = (cb * 2) & 15;
                sts32(sQw + (unsigned)((r0 * 8 + (ch ^ (r0 & 7))) * 16 + off), lo);
                int r1 = r0 + 8;
                sts32(sQw + (unsigned)((r1 * 8 + (ch ^ (r1 & 7))) * 16 + off), hi);
            }
        }
        __syncthreads();   // sQ written; sX/sW region free for K tiles
    }

    // ================= K pipeline prologue =================
    for (int i = tid; i < 1024; i += 256) {
        int row = i >> 3, c = i & 7;
        cp16(&sK4[row * 8 + (c ^ (row & 7))], gk + (size_t)row * ZD + c * 8);
    }
    CP_COMMIT();
    {
        const __half *gk1 = gk + (size_t)128 * ZD;
        uint4 *buf = sK4 + 1024;
        for (int i = tid; i < 1024; i += 256) {
            int row = i >> 3, c = i & 7;
            cp16(&buf[row * 8 + (c ^ (row & 7))], gk1 + (size_t)row * ZD + c * 8);
        }
        CP_COMMIT();
    }
    CP_WAIT(1);          // K0 ready (K1 in flight)
    __syncthreads();

    const unsigned sQb = smem_u32(sQ4);

    float m[2], s[2];
    m[0] = -INFINITY; s[0] = 0.f; m[1] = -INFINITY; s[1] = 0.f;

    unsigned bank[8][2];

    const int brow_off = wc * 64 + (lane & 7) + ((lane >> 4) & 1) * 8;
    const int bco = (lane >> 3) & 1;
    const int qrow0 = 16 * wr + (lane & 15);
    const int qch_sel = (lane >> 4);

#pragma unroll 1
    for (int kt = 0; kt < 16; kt++) {
        const unsigned sKb = smem_u32(sK4 + (kt & 1) * 1024);

        // ---- MMA(tile kt): stream Q frag per kk; kk=0 zero-init ----
#pragma unroll
        for (int kk = 0; kk < 4; kk++) {
            unsigned a0, a1, a2, a3;
            {
                int ch = (kk * 2 + qch_sel) ^ (qrow0 & 7);
                ldsm4(sQb + (unsigned)((qrow0 * 8 + ch) * 16), a0, a1, a2, a3);
            }
#pragma unroll
            for (int n16 = 0; n16 < 4; n16++) {
                int brow = n16 * 16 + brow_off;
                int bch = (kk * 2 + bco) ^ (brow & 7);
                unsigned b0, b1, b2, b3;
                ldsm4(sKb + (unsigned)((brow * 8 + bch) * 16), b0, b1, b2, b3);
                if (kk == 0) {
                    mma_f16_f16_z(bank[n16 * 2][0],     bank[n16 * 2][1],
                                  a0, a1, a2, a3, b0, b1);
                    mma_f16_f16_z(bank[n16 * 2 + 1][0], bank[n16 * 2 + 1][1],
                                  a0, a1, a2, a3, b2, b3);
                } else {
                    mma_f16_f16(bank[n16 * 2][0],     bank[n16 * 2][1],
                                a0, a1, a2, a3, b0, b1);
                    mma_f16_f16(bank[n16 * 2 + 1][0], bank[n16 * 2 + 1][1],
                                a0, a1, a2, a3, b2, b3);
                }
            }
        }
        epi_bank(bank, m, s);

        __syncthreads();   // all warps done reading buf[kt&1]

        if (kt + 2 < 16) {
            const __half *gkt = gk + (size_t)(kt + 2) * 128 * ZD;
            uint4 *buf = sK4 + (kt & 1) * 1024;
            for (int i = tid; i < 1024; i += 256) {
                int row = i >> 3, c = i & 7;
                cp16(&buf[row * 8 + (c ^ (row & 7))], gkt + (size_t)row * ZD + c * 8);
            }
            CP_COMMIT();
            CP_WAIT(1);    // K(kt+1) done (FIFO)
        } else if (kt + 1 < 16) {
            CP_WAIT(0);    // drain K15
        }
        __syncthreads();
    }

    // merge (m,s) across the 4 lanes of each quad (slice = 64-col half row)
#pragma unroll
    for (int idx = 0; idx < 2; idx++) {
        float mm = m[idx], ss = s[idx];
#pragma unroll
        for (int off = 1; off <= 2; off <<= 1) {
            float mo = __shfl_xor_sync(0xffffffffu, mm, off);
            float so = __shfl_xor_sync(0xffffffffu, ss, off);
            float mn = fmaxf(mm, mo);
            ss = ss * ex2f(mm - mn) + so * ex2f(mo - mn);
            mm = mn;
        }
        m[idx] = mm; s[idx] = ss;
    }
    if ((lane & 3) == 0) {
#pragma unroll
        for (int idx = 0; idx < 2; idx++) {
            sM[w][idx][lane >> 2] = m[idx];
            sS[w][idx][lane >> 2] = s[idx];
        }
    }
    __syncthreads();

    // warps 0-3: merge col-half partner (w+4), per-row lse, warp-sum
    float contrib = 0.f;
    if (wc == 0 && (lane & 3) == 0) {
#pragma unroll
        for (int idx = 0; idx < 2; idx++) {
            float ma = sM[w][idx][lane >> 2], sa = sS[w][idx][lane >> 2];
            float mb = sM[w + 4][idx][lane >> 2], sb = sS[w + 4][idx][lane >> 2];
            float mn = fmaxf(ma, mb);
            float ss = sa * ex2f(ma - mn) + sb * ex2f(mb - mn);
            contrib += mn + lg2f(ss);
        }
    }
    if (wc == 0) {
#pragma unroll
        for (int off = 16; off; off >>= 1)
            contrib += __shfl_xor_sync(0xffffffffu, contrib, off);
        if (lane == 0) warpSum[wr] = contrib;
    }
    __syncthreads();

    // publish partial, then the last CTA to finish reduces everything
    if (tid == 0) {
        g_partial[blockIdx.y * 32 + blockIdx.x] =
            warpSum[0] + warpSum[1] + warpSum[2] + warpSum[3];
        __threadfence();
        unsigned prev = atomicAdd(&g_done, 1u);
        amLast = (prev == 32u * NH - 1u);
    }
    __syncthreads();

    if (amLast) {
        __threadfence();   // make all g_partial writes visible
        red[tid] = (g_partial[tid]       + g_partial[tid + 256]) +
                   (g_partial[tid + 512] + g_partial[tid + 768]);
        __syncthreads();
        for (int st = 128; st > 0; st >>= 1) {
            if (tid < st) red[tid] += red[tid + st];
            __syncthreads();
        }
        if (tid == 0) {
            const double C = -(11.313708498984760390 * 0.69314718055994530942);
            out[0] = (float)(C * (double)red[0]);
        }
    }
}

// ---------------------------------------------------------------------------
extern "C" void kernel_launch(void *const *d_in, const int *in_sizes, int n_in,
                              void *d_out, int out_size) {
    (void)in_sizes; (void)n_in; (void)out_size;
    const float *x  = (const float *)d_in[0];
    const float *Wq = (const float *)d_in[1];
    const float *Wk = (const float *)d_in[2];
    float *out = (float *)d_out;

    static bool attr_set = false;
    if (!attr_set) {
        cudaFuncSetAttribute(kproj_kernel, cudaFuncAttributeMaxDynamicSharedMemorySize, 49152);
        cudaFuncSetAttribute(attn_lse_kernel, cudaFuncAttributeMaxDynamicSharedMemorySize, 40960);
        attr_set = true;
    }

    prep_kernel<<<768, 256>>>(x, Wq, Wk);
    kproj_kernel<<<dim3(16, 32), 256, 49152>>>();
    attn_lse_kernel<<<dim3(32, 32), 256, 40960>>>(out);
}